// round 2
// baseline (speedup 1.0000x reference)
#include <cuda_runtime.h>
#include <cstdint>

// out = logits * S, with margin M subtracted at (row, label) pre-scale for label != -1.
// logits: [4096, 50257] fp32 ; labels: [4096] int32 (harness lowers int64) ; out: fp32.

static constexpr float S = 64.0f;
static constexpr float M = 0.35f;
static constexpr long long NUM_CLASSES = 50257;

__global__ void scale_kernel(const float4* __restrict__ in, float4* __restrict__ out,
                             long long n4) {
    long long i = (long long)blockIdx.x * blockDim.x + threadIdx.x;
    if (i < n4) {
        float4 v = in[i];
        v.x *= S; v.y *= S; v.z *= S; v.w *= S;
        out[i] = v;
    }
}

__global__ void margin_fixup_kernel(const float* __restrict__ in,
                                    const int* __restrict__ labels,
                                    float* __restrict__ out, int batch) {
    int row = blockIdx.x * blockDim.x + threadIdx.x;
    if (row < batch) {
        int lbl = labels[row];
        if (lbl != -1 && lbl >= 0 && lbl < NUM_CLASSES) {
            long long idx = (long long)row * NUM_CLASSES + lbl;
            out[idx] = (in[idx] - M) * S;
        }
    }
}

extern "C" void kernel_launch(void* const* d_in, const int* in_sizes, int n_in,
                              void* d_out, int out_size) {
    const float* logits = (const float*)d_in[0];
    const int* labels = (const int*)d_in[1];
    float* out = (float*)d_out;

    long long total = (long long)in_sizes[0];      // 4096 * 50257, divisible by 4
    long long n4 = total / 4;
    int batch = in_sizes[1];

    const int threads = 256;
    long long blocks = (n4 + threads - 1) / threads;
    scale_kernel<<<(unsigned)blocks, threads>>>(
        (const float4*)logits, (float4*)out, n4);

    int fb = (batch + threads - 1) / threads;
    margin_fixup_kernel<<<fb, threads>>>(logits, labels, out, batch);
}